// round 17
// baseline (speedup 1.0000x reference)
#include <cuda_runtime.h>
#include <cuda_bf16.h>

#define ROW_N 4096
#define THREADS 256
#define RC 0.70710678118654752440f

// Monarch FFT, out = Re(FFT(x)) per 4096-pt row; P = Q = 64, radix-8x8,
// Hermitian symmetry everywhere. 256 thr/CTA, 4 CTAs/SM, XOR-16 swizzled C.
// All compile-time-indexed twiddles are constexpr immediates (no LDS,
// FFMA-imm dual rate); phase B templated on k1a (uniform 4-way dispatch).
// NOTE: twiddle helpers are __host__ __device__ constexpr (nvcc w/o
// --expt-relaxed-constexpr rejects host-constexpr calls from device code).

// ---- constexpr twiddle tables: cos(pi k/32) ----
__host__ __device__ constexpr double c32(int k) {
    return (k ==  0) ? 1.0
         : (k ==  1) ? 0.99518472667219682
         : (k ==  2) ? 0.98078528040323044
         : (k ==  3) ? 0.95694033573220886
         : (k ==  4) ? 0.92387953251128674
         : (k ==  5) ? 0.88192126434835502
         : (k ==  6) ? 0.83146961230254524
         : (k ==  7) ? 0.77301045336273699
         : (k ==  8) ? 0.70710678118654752
         : (k ==  9) ? 0.63439328416364549
         : (k == 10) ? 0.55557023301960222
         : (k == 11) ? 0.47139673682599764
         : (k == 12) ? 0.38268343236508977
         : (k == 13) ? 0.29028467725446233
         : (k == 14) ? 0.19509032201612827
         : (k == 15) ? 0.09801714032956060
         : 0.0;
}
__host__ __device__ constexpr float w64c(int t) {   // cos(2 pi t / 64)
    return (float)(((t & 63) <= 16) ?  c32(t & 63)
                 : ((t & 63) <= 32) ? -c32(32 - (t & 63))
                 : ((t & 63) <= 48) ? -c32((t & 63) - 32)
                 :                     c32(64 - (t & 63)));
}
__host__ __device__ constexpr double s32h(int t) {  // sin(2 pi t/64), t in [0,32]
    return (t <= 16) ? c32(16 - t) : c32(t - 16);
}
__host__ __device__ constexpr float w64s(int t) {   // sin(2 pi t / 64)
    return (float)(((t & 63) <= 32) ? s32h(t & 63) : -s32h((t & 63) - 32));
}
// T64[t] = (w64c(t), -w64s(t))

__device__ __forceinline__ float2 cmulf(float2 a, float2 b) {
    return make_float2(fmaf(a.x, b.x, -(a.y * b.y)),
                       fmaf(a.x, b.y,   a.y * b.x));
}

// ---- packed f32x2 helpers (register-pair data only) ----
__device__ __forceinline__ float2 p_add(float2 a, float2 b) {
    unsigned long long r, ua = *(unsigned long long*)&a, ub = *(unsigned long long*)&b;
    asm("add.rn.f32x2 %0, %1, %2;" : "=l"(r) : "l"(ua), "l"(ub));
    return *(float2*)&r;
}
__device__ __forceinline__ float2 p_fma(float2 a, float2 b, float2 c) {
    unsigned long long r, ua = *(unsigned long long*)&a, ub = *(unsigned long long*)&b,
                       uc = *(unsigned long long*)&c;
    asm("fma.rn.f32x2 %0, %1, %2, %3;" : "=l"(r) : "l"(ua), "l"(ub), "l"(uc));
    return *(float2*)&r;
}
__device__ __forceinline__ float2 p_sub(float2 a, float2 b) {
    return p_fma(b, make_float2(-1.f, -1.f), a);
}

// (bx,by) += h * e^{-2pi i M/8}, sqrt2 terms inline
template<int M>
__device__ __forceinline__ void rot_add(float hx, float hy, float& bx, float& by)
{
    if constexpr (M == 0)      { bx += hx; by += hy; }
    else if constexpr (M == 1) { bx = fmaf(RC, hx + hy, bx); by = fmaf(RC, hy - hx, by); }
    else if constexpr (M == 2) { bx += hy; by -= hx; }
    else if constexpr (M == 3) { bx = fmaf(RC, hy - hx, bx); by = fmaf(-RC, hx + hy, by); }
    else if constexpr (M == 4) { bx -= hx; by -= hy; }
    else if constexpr (M == 5) { bx = fmaf(-RC, hx + hy, bx); by = fmaf(RC, hx - hy, by); }
    else if constexpr (M == 6) { bx -= hy; by += hx; }
    else                       { bx = fmaf(RC, hx - hy, bx); by = fmaf(RC, hx + hy, by); }
}

template<int K2>
__device__ __forceinline__ void gather8(const float (&Hx)[8], const float (&Hy)[8],
                                        float& bx, float& by)
{
    bx = Hx[0]; by = Hy[0];
    rot_add<(1*K2)&7>(Hx[1],Hy[1],bx,by);
    rot_add<(2*K2)&7>(Hx[2],Hy[2],bx,by);
    rot_add<(3*K2)&7>(Hx[3],Hy[3],bx,by);
    rot_add<(4*K2)&7>(Hx[4],Hy[4],bx,by);
    rot_add<(5*K2)&7>(Hx[5],Hy[5],bx,by);
    rot_add<(6*K2)&7>(Hx[6],Hy[6],bx,by);
    rot_add<(7*K2)&7>(Hx[7],Hy[7],bx,by);
}

// c * e^{-2pi i M/8}
template<int M>
__device__ __forceinline__ float2 crot(float2 c)
{
    if constexpr (M == 0)      return c;
    else if constexpr (M == 1) return make_float2( RC*(c.x+c.y),  RC*(c.y-c.x));
    else if constexpr (M == 2) return make_float2( c.y, -c.x);
    else if constexpr (M == 3) return make_float2( RC*(c.y-c.x), -RC*(c.x+c.y));
    else if constexpr (M == 4) return make_float2(-c.x, -c.y);
    else if constexpr (M == 5) return make_float2(-RC*(c.x+c.y),  RC*(c.x-c.y));
    else if constexpr (M == 6) return make_float2(-c.y,  c.x);
    else                       return make_float2( RC*(c.x-c.y),  RC*(c.x+c.y));
}

// Re( F * e^{-2pi i M/8} )
template<int M>
__device__ __forceinline__ float rot_re(float2 F)
{
    if constexpr (M == 0)      return  F.x;
    else if constexpr (M == 1) return  RC*(F.x+F.y);
    else if constexpr (M == 2) return  F.y;
    else if constexpr (M == 3) return  RC*(F.y-F.x);
    else if constexpr (M == 4) return -F.x;
    else if constexpr (M == 5) return -RC*(F.x+F.y);
    else if constexpr (M == 6) return -F.y;
    else                       return  RC*(F.x-F.y);
}

// complex multiply by compile-time w64^T
template<int T>
__device__ __forceinline__ float2 cmul_w64(float2 E)
{
    constexpr float Wx = w64c(T & 63);
    constexpr float Wy = -w64s(T & 63);
    return make_float2(fmaf(E.x, Wx, -(E.y * Wy)), fmaf(E.x, Wy, E.y * Wx));
}

// Stage-2 one p1: 8 swizzled loads -> packed fold -> immediate twiddles.
template<int P1, int G2>
__device__ __forceinline__ void s2_p1(const float2* __restrict__ Cs,
                                      int k, float (&acc)[16])
{
    const int XA = k ^ P1;
    const int XB = k ^ (P1 + 8);
    const float2 u0 = crot<0        >(Cs[(P1 +  0)*64 + XA]);
    const float2 u1 = crot<(G2*1)&7>(Cs[(P1 +  8)*64 + XB]);
    const float2 u2 = crot<(G2*2)&7>(Cs[(P1 + 16)*64 + XA]);
    const float2 u3 = crot<(G2*3)&7>(Cs[(P1 + 24)*64 + XB]);
    const float2 u4 = crot<(G2*4)&7>(Cs[(P1 + 32)*64 + XA]);
    const float2 u5 = crot<(G2*5)&7>(Cs[(P1 + 40)*64 + XB]);
    const float2 u6 = crot<(G2*6)&7>(Cs[(P1 + 48)*64 + XA]);
    const float2 u7 = crot<(G2*7)&7>(Cs[(P1 + 56)*64 + XB]);

    const float2 s0 = p_add(u0,u4), s1 = p_add(u1,u5);
    const float2 s2 = p_add(u2,u6), s3 = p_add(u3,u7);
    const float2 Pp = p_add(s0,s2), Qq = p_add(s1,s3);
    const float2 Rr = p_sub(s0,s2), Ss = p_sub(s1,s3);
    const float2 E0 = p_add(Pp,Qq), E2 = p_sub(Pp,Qq);
    const float2 Ssw = make_float2(Ss.y, -Ss.x);
    const float2 E1 = p_add(Rr,Ssw), E3 = p_sub(Rr,Ssw);

    {   const float2 F = cmul_w64<P1*(G2+0)>(E0);
        acc[ 0] += rot_re<0        >(F);
        acc[ 1] += rot_re<(P1*1)&7>(F);
        acc[ 2] += rot_re<(P1*2)&7>(F);
        acc[ 3] += rot_re<(P1*3)&7>(F); }
    {   const float2 F = cmul_w64<P1*(G2+2)>(E1);
        acc[ 4] += rot_re<0        >(F);
        acc[ 5] += rot_re<(P1*1)&7>(F);
        acc[ 6] += rot_re<(P1*2)&7>(F);
        acc[ 7] += rot_re<(P1*3)&7>(F); }
    {   const float2 F = cmul_w64<P1*(G2+4)>(E2);
        acc[ 8] += rot_re<0        >(F);
        acc[ 9] += rot_re<(P1*1)&7>(F);
        acc[10] += rot_re<(P1*2)&7>(F);
        acc[11] += rot_re<(P1*3)&7>(F); }
    {   const float2 F = cmul_w64<P1*(G2+6)>(E3);
        acc[12] += rot_re<0        >(F);
        acc[13] += rot_re<(P1*1)&7>(F);
        acc[14] += rot_re<(P1*2)&7>(F);
        acc[15] += rot_re<(P1*3)&7>(F); }
}

template<int G2, int Qh>
__device__ __forceinline__ void stage2_run(const float2* __restrict__ Cs,
                                           int k, float (&acc)[16])
{
    s2_p1<Qh,     G2>(Cs, k, acc);
    s2_p1<Qh + 2, G2>(Cs, k, acc);
    s2_p1<Qh + 4, G2>(Cs, k, acc);
    s2_p1<Qh + 6, G2>(Cs, k, acc);
}

// ---- phase B templated on K1A (0..3): load H + cur/stp (before sync) ----
template<int K1A>
__device__ __forceinline__ void phaseB_load(const float2* __restrict__ Gs,
    const float2* __restrict__ T64, const float2* __restrict__ Tf, int p,
    float (&HxA)[8], float (&HyA)[8], float (&HxB)[8], float (&HyB)[8],
    float2& curA, float2& curB, float2& stp)
{
    if constexpr (K1A == 0) {
        #define LH(q1) { const float2 g = Gs[(q1)*64 + p]; \
            HxA[q1] = g.x; HyA[q1] = 0.f; \
            constexpr float Wx = w64c(4*(q1)), Wy = -w64s(4*(q1)); \
            HxB[q1] = g.y * Wx; HyB[q1] = g.y * Wy; }
        LH(0) LH(1) LH(2) LH(3) LH(4) LH(5) LH(6) LH(7)
        #undef LH
        curA = make_float2(1.f, 0.f);
    } else {
        #define LHD(q1) { const float2 g = Gs[(K1A*8 + (q1))*64 + p]; \
            constexpr float Wx = w64c((q1)*K1A), Wy = -w64s((q1)*K1A); \
            HxA[q1] = fmaf(g.x, Wx, -(g.y * Wy)); \
            HyA[q1] = fmaf(g.x, Wy,   g.y * Wx); }
        LHD(0) LHD(1) LHD(2) LHD(3) LHD(4) LHD(5) LHD(6) LHD(7)
        #undef LHD
        #define LHC(q1) { const float2 g = Gs[((4-K1A)*8 + (q1))*64 + p]; \
            constexpr float Wx = w64c((q1)*(K1A+4)), Wy = -w64s((q1)*(K1A+4)); \
            HxB[q1] = fmaf(g.x, Wx,   g.y * Wy); \
            HyB[q1] = fmaf(g.x, Wy, -(g.y * Wx)); }
        LHC(0) LHC(1) LHC(2) LHC(3) LHC(4) LHC(5) LHC(6) LHC(7)
        #undef LHC
        const int ta = p * K1A;
        curA = cmulf(T64[ta >> 6], Tf[ta & 63]);
    }
    const int tb = p * (K1A + 4);
    curB = cmulf(T64[tb >> 6], Tf[tb & 63]);
    const int ts = 8 * p;
    stp = cmulf(T64[ts >> 6], Tf[ts & 63]);
}

// ---- phase B: gather + C writes (after sync) ----
template<int K1A>
__device__ __forceinline__ void phaseB_store(float2* __restrict__ Cs, int p,
    float2 T64p,
    const float (&HxA)[8], const float (&HyA)[8],
    const float (&HxB)[8], const float (&HyB)[8],
    float2 curA, float2 curB, float2 stp)
{
    const int pxor = p & 15;
    float2* __restrict__ Crow = Cs + p * 64;
    #define CSW(c) Crow[(c) ^ pxor]
    #define S1A(K2) { \
        float bx, by; gather8<K2>(HxA, HyA, bx, by); \
        CSW(K1A + 8 * K2) = make_float2(fmaf(bx, curA.x, -(by * curA.y)), \
                                        fmaf(bx, curA.y,   by * curA.x)); \
        if constexpr (K1A + 8 * K2 > 0) { \
            const float mx = fmaf(T64p.x, curA.x,   T64p.y * curA.y);  \
            const float my = fmaf(T64p.y, curA.x, -(T64p.x * curA.y)); \
            CSW(64 - (K1A + 8 * K2)) = make_float2(                    \
                fmaf(bx, mx,   by * my),                               \
                fmaf(bx, my, -(by * mx)));                             \
        } \
        curA = cmulf(curA, stp); }
    S1A(0) S1A(1) S1A(2) S1A(3)
    #undef S1A
    if constexpr (K1A == 0) {                      // k = 32 (self-mirrored)
        float bx, by; gather8<4>(HxA, HyA, bx, by);
        CSW(32) = make_float2(fmaf(bx, curA.x, -(by * curA.y)),
                              fmaf(bx, curA.y,   by * curA.x));
    }
    #define S1B(K2) { \
        float bx, by; gather8<K2>(HxB, HyB, bx, by); \
        CSW((K1A+4) + 8 * K2) = make_float2(fmaf(bx, curB.x, -(by * curB.y)), \
                                            fmaf(bx, curB.y,   by * curB.x)); \
        { \
            const float mx = fmaf(T64p.x, curB.x,   T64p.y * curB.y);  \
            const float my = fmaf(T64p.y, curB.x, -(T64p.x * curB.y)); \
            CSW(64 - ((K1A+4) + 8 * K2)) = make_float2(                \
                fmaf(bx, mx,   by * my),                               \
                fmaf(bx, my, -(by * mx)));                             \
        } \
        curB = cmulf(curB, stp); }
    S1B(0) S1B(1) S1B(2) S1B(3)
    #undef S1B
    #undef CSW
}

__global__ void __launch_bounds__(THREADS, 4)
monarch_fft_kernel(const float* __restrict__ x, float* __restrict__ out)
{
    __shared__ float2 Cs[64 * 64];   // C[p][k^(p&15)], XOR-swizzled (32 KB)
    __shared__ float2 T64[64];       // e^{-2pi i t/64}   (runtime-index uses)
    __shared__ float2 Tf [64];       // e^{-2pi i t/4096}
    float2* Gs  = Cs;                // phase-A G storage overlay
    float*  Pov = (float*)Cs;        // stage-2 partial overlay

    const int tid = threadIdx.x;
    const int row = blockIdx.x;

    if (tid < 64) {
        float s, c;
        __sincosf(-6.28318530717958647692f * (float)tid * (1.0f / 64.0f), &s, &c);
        T64[tid] = make_float2(c, s);
        __sincosf(-6.28318530717958647692f * (float)tid * (1.0f / 4096.0f), &s, &c);
        Tf[tid] = make_float2(c, s);
    }

    // ===== Phase A: thread (p, q1a): scalar real DFT-8 over q2, twice =======
    const int p = tid & 63;
    {
        const int q1a = tid >> 6;                  // 0..3
        #pragma unroll
        for (int pass = 0; pass < 2; pass++) {
            const int q1 = q1a + 4 * pass;
            const float* __restrict__ xr = x + (size_t)row * ROW_N + p + 64 * q1;
            const float a0 = xr[0],    a1 = xr[512],  a2 = xr[1024], a3 = xr[1536];
            const float a4 = xr[2048], a5 = xr[2560], a6 = xr[3072], a7 = xr[3584];

            const float s0 = a0 + a4, d0 = a0 - a4;
            const float s1 = a1 + a5, d1 = a1 - a5;
            const float s2 = a2 + a6, d2 = a2 - a6;
            const float s3 = a3 + a7, d3 = a3 - a7;

            const float e02 = s0 + s2, o13 = s1 + s3;
            const float t1 = RC * (d1 - d3);
            const float t2 = RC * (d1 + d3);

            Gs[(0 * 8 + q1) * 64 + p] = make_float2(e02 + o13, e02 - o13);
            Gs[(1 * 8 + q1) * 64 + p] = make_float2(d0 + t1, -(d2 + t2));
            Gs[(2 * 8 + q1) * 64 + p] = make_float2(s0 - s2, -(s1 - s3));
            Gs[(3 * 8 + q1) * 64 + p] = make_float2(d0 - t1,   d2 - t2);
        }
    }
    __syncthreads();

    // ===== Phase B: load (templated on k1a), sync, store =====
    const int k1c = tid >> 6;                      // 0..3
    float HxA[8], HyA[8], HxB[8], HyB[8];
    float2 curA, curB, stp;
    switch (k1c) {
        case 0: phaseB_load<0>(Gs, T64, Tf, p, HxA, HyA, HxB, HyB, curA, curB, stp); break;
        case 1: phaseB_load<1>(Gs, T64, Tf, p, HxA, HyA, HxB, HyB, curA, curB, stp); break;
        case 2: phaseB_load<2>(Gs, T64, Tf, p, HxA, HyA, HxB, HyB, curA, curB, stp); break;
        default:phaseB_load<3>(Gs, T64, Tf, p, HxA, HyA, HxB, HyB, curA, curB, stp); break;
    }
    const float2 T64p = T64[p];
    __syncthreads();                               // all G reads complete

    switch (k1c) {
        case 0: phaseB_store<0>(Cs, p, T64p, HxA, HyA, HxB, HyB, curA, curB, stp); break;
        case 1: phaseB_store<1>(Cs, p, T64p, HxA, HyA, HxB, HyB, curA, curB, stp); break;
        case 2: phaseB_store<2>(Cs, p, T64p, HxA, HyA, HxB, HyB, curA, curB, stp); break;
        default:phaseB_store<3>(Cs, p, T64p, HxA, HyA, HxB, HyB, curA, curB, stp); break;
    }
    __syncthreads();

    // ===== Stage 2: k = tid&63, cls = tid>>6: G2 = cls&1, Qh = cls>>1 =======
    const int k   = tid & 63;
    const int cls = tid >> 6;                      // 0..3
    float* __restrict__ outr = out + (size_t)row * ROW_N;

    float acc[16];
    #pragma unroll
    for (int i = 0; i < 16; i++) acc[i] = 0.f;

    switch (cls) {
        case 0: stage2_run<0,0>(Cs, k, acc); break;
        case 1: stage2_run<1,0>(Cs, k, acc); break;
        case 2: stage2_run<0,1>(Cs, k, acc); break;
        default:stage2_run<1,1>(Cs, k, acc); break;
    }

    // lone element m = 2048 (needs Cs BEFORE overlay): sum_p (-1)^p Re C[p,0]
    if (tid == 0) {
        float a2 = 0.f;
        #pragma unroll 8
        for (int pp = 0; pp < 64; pp += 2)
            a2 += Cs[pp * 64 + (pp & 15)].x
                - Cs[(pp + 1) * 64 + ((pp + 1) & 15)].x;
        outr[2048] = a2;
    }
    __syncthreads();                               // all Cs reads complete

    if (cls >= 2) {                                // Qh = 1 halves write partials
        const int u = tid - 128;                   // 0..127
        #pragma unroll
        for (int i = 0; i < 16; i++) Pov[i * 128 + u] = acc[i];
    }
    __syncthreads();

    if (cls < 2) {                                 // Qh = 0 combines + stores
        const int G2 = cls;
        #pragma unroll
        for (int i = 0; i < 16; i++) acc[i] += Pov[i * 128 + G2 * 64 + k];
        #pragma unroll
        for (int m = 0; m < 4; m++) {
            #pragma unroll
            for (int j2 = 0; j2 < 4; j2++) {
                const int j  = (G2 + 2 * m) + 8 * j2;    // 0..31
                const int mj = j * 64 + k;               // 0..2047
                const float v = acc[m * 4 + j2];
                outr[mj] = v;                            // coalesced
                if (mj >= 1) outr[ROW_N - mj] = v;       // mirror (incl col 0)
            }
        }
    }
}

extern "C" void kernel_launch(void* const* d_in, const int* in_sizes, int n_in,
                              void* d_out, int out_size)
{
    const float* x = (const float*)d_in[0];
    const int nrows = in_sizes[0] / ROW_N;         // 4096 rows
    if (nrows <= 0) return;
    monarch_fft_kernel<<<nrows, THREADS>>>(x, (float*)d_out);
}